// round 12
// baseline (speedup 1.0000x reference)
#include <cuda_runtime.h>
#include <math_constants.h>

#define BN 2
#define NP 65536
#define MR 128
#define NS 6
#define KK 2048
#define NBS (BN*NS)

#define FT 256          // FPS threads (8 warps -> 2 per SMSP)
#define NW (FT/32)      // 8 warps
#define MAXP 12         // max candidate pairs per thread
#define CAP (FT*2*MAXP) // 6144 candidates
#define SMEM_FPS (CAP*16)    // float4 sP[CAP]

typedef unsigned long long u64;
__device__ __forceinline__ u64 f2pack(float lo, float hi) {
    u64 r; asm("mov.b64 %0,{%1,%2};" : "=l"(r) : "f"(lo), "f"(hi)); return r;
}
__device__ __forceinline__ void f2unpack(u64 v, float& lo, float& hi) {
    asm("mov.b64 {%0,%1},%2;" : "=f"(lo), "=f"(hi) : "l"(v));
}
__device__ __forceinline__ u64 add2(u64 a, u64 b) {
    u64 r; asm("add.rn.f32x2 %0,%1,%2;" : "=l"(r) : "l"(a), "l"(b)); return r;
}
__device__ __forceinline__ u64 mul2(u64 a, u64 b) {
    u64 r; asm("mul.rn.f32x2 %0,%1,%2;" : "=l"(r) : "l"(a), "l"(b)); return r;
}

// ---- scratch (__device__ globals: allocation-free) ----
__device__ float4        g_comp[NBS][NP];   // compacted candidates (x,y,z, orig idx bits)
__device__ float         g_dmin[NBS][NP];   // FPS fallback dmin (cnt > CAP only)
__device__ unsigned char g_sec [BN][NP];    // sector code 0..6, 255 = invalid
__device__ int g_cnt[BN][7];                // per-sector counts; [6] = valid-but-sector-6

// ---- classify: 2 points/thread, packed-f32x2 distances (exact), deferred sqrt cleanup ----
__global__ void __launch_bounds__(256) k_classify(const float* __restrict__ points,
                                                  const float* __restrict__ rois) {
    __shared__ __align__(8) float sncx[MR], sncy[MR], sncz[MR];  // NEGATED centers
    __shared__ float sthr[MR];                                   // maxdim + 1.6
    int b = blockIdx.y;
    int tid = threadIdx.x;
    if (tid < MR) {
        const float* r = rois + (b * MR + tid) * 7;
        float cx = r[0], cy = r[1], cz = r[2];
        float dx = r[3], dy = r[4], dz = r[5];
        cz = __fadd_rn(cz, __fmul_rn(dz, 0.5f));
        float hx = __fmul_rn(dx, 0.5f), hy = __fmul_rn(dy, 0.5f), hz = __fmul_rn(dz, 0.5f);
        float md = __fsqrt_rn(__fadd_rn(__fadd_rn(__fmul_rn(hx, hx), __fmul_rn(hy, hy)),
                                        __fmul_rn(hz, hz)));
        sncx[tid] = -cx; sncy[tid] = -cy; sncz[tid] = -cz;
        sthr[tid] = __fadd_rn(md, 1.6f);
    }
    __syncthreads();

    int i0 = blockIdx.x * 512 + tid;
    int i1 = i0 + 256;
    const float* pA = points + ((size_t)b * NP + i0) * 3;
    const float* pB = points + ((size_t)b * NP + i1) * 3;
    float pxA = pA[0], pyA = pA[1], pzA = pA[2];
    float pxB = pB[0], pyB = pB[1], pzB = pB[2];
    u64 pxa = f2pack(pxA, pxA), pya = f2pack(pyA, pyA), pza = f2pack(pzA, pzA);
    u64 pxb = f2pack(pxB, pxB), pyb = f2pack(pyB, pyB), pzb = f2pack(pzB, pzB);

    // p - c == p + (-c) exactly (IEEE). Packed halves round identically to scalar rn.
    float m1A = CUDART_INF_F, m2A = CUDART_INF_F; int biA = 0;
    float m1B = CUDART_INF_F, m2B = CUDART_INF_F; int biB = 0;
    #pragma unroll 4
    for (int m = 0; m < MR / 2; m++) {
        u64 ncx = *(const u64*)&sncx[2 * m];
        u64 ncy = *(const u64*)&sncy[2 * m];
        u64 ncz = *(const u64*)&sncz[2 * m];
        u64 axA = add2(pxa, ncx), ayA = add2(pya, ncy), azA = add2(pza, ncz);
        u64 d2A = add2(add2(mul2(axA, axA), mul2(ayA, ayA)), mul2(azA, azA));
        u64 axB = add2(pxb, ncx), ayB = add2(pyb, ncy), azB = add2(pzb, ncz);
        u64 d2B = add2(add2(mul2(axB, axB), mul2(ayB, ayB)), mul2(azB, azB));
        float a0, a1, b0, b1;
        f2unpack(d2A, a0, a1);
        f2unpack(d2B, b0, b1);
        float mx = fmaxf(a0, m1A); m2A = fminf(m2A, mx);
        if (a0 < m1A) { m1A = a0; biA = 2 * m; }
        mx = fmaxf(a1, m1A); m2A = fminf(m2A, mx);
        if (a1 < m1A) { m1A = a1; biA = 2 * m + 1; }
        mx = fmaxf(b0, m1B); m2B = fminf(m2B, mx);
        if (b0 < m1B) { m1B = b0; biB = 2 * m; }
        mx = fmaxf(b1, m1B); m2B = fminf(m2B, mx);
        if (b1 < m1B) { m1B = b1; biB = 2 * m + 1; }
    }

    #pragma unroll
    for (int pt = 0; pt < 2; pt++) {
        float px = pt ? pxB : pxA, py = pt ? pyB : pyA, pz = pt ? pzB : pzA;
        float m1 = pt ? m1B : m1A, m2 = pt ? m2B : m2A;
        int bi = pt ? biB : biA;
        float s1 = __fsqrt_rn(m1);
        // d2-argmin == sqrt-argmin unless two d2 round to the same sqrt; redo exactly.
        if (__fsqrt_rn(m2) == s1) {
            float bsv = CUDART_INF_F; int bi2 = 0;
            for (int m = 0; m < MR; m++) {
                float ax = __fadd_rn(px, sncx[m]);
                float ay = __fadd_rn(py, sncy[m]);
                float az = __fadd_rn(pz, sncz[m]);
                float d2 = __fadd_rn(__fadd_rn(__fmul_rn(ax, ax), __fmul_rn(ay, ay)),
                                     __fmul_rn(az, az));
                float sd = __fsqrt_rn(d2);
                if (sd < bsv) { bsv = sd; bi2 = m; }
            }
            s1 = bsv; bi = bi2;
        }
        bool valid = s1 < sthr[bi];
        float ang = __fadd_rn(atan2f(py, px), 3.14159265358979323846f);
        float fs  = floorf(__fdiv_rn(ang, 1.04719755119659774615f));
        fs = fminf(fmaxf(fs, 0.0f), 6.0f);
        int s = (int)fs;
        g_sec[b][pt ? i1 : i0] = valid ? (unsigned char)s : (unsigned char)255;
    }
}

// ---- compact: vcmpeq4 counting + R10-proven STABLE per-lane scatter ----
__global__ void __launch_bounds__(1024) k_compact(const float* __restrict__ points) {
    int bs = blockIdx.x;
    int tid = threadIdx.x, lane = tid & 31, wid = tid >> 5;
    __shared__ int wcnt[32];
    __shared__ int woff[32];

    if (bs >= NBS) {  // count-only: sector 6 of batch b
        int b = bs - NBS;
        const unsigned* sec4 = (const unsigned*)g_sec[b];
        int c = 0;
        for (int i = tid; i < NP / 4; i += 1024)
            c += __popc(__vcmpeq4(sec4[i], 0x06060606u) & 0x01010101u);
        c = __reduce_add_sync(0xffffffffu, c);
        if (lane == 0) wcnt[wid] = c;
        __syncthreads();
        if (tid == 0) {
            int t = 0;
            for (int w = 0; w < 32; w++) t += wcnt[w];
            g_cnt[b][6] = t;
        }
        return;
    }

    int b = bs / NS, s = bs - b * NS;
    const unsigned char* sec = g_sec[b];
    const float* pts = points + (size_t)b * NP * 3;
    const int R = NP / 32;           // 2048 points per warp, contiguous (stable order)
    int r0 = wid * R;
    unsigned pat = 0x01010101u * (unsigned)s;

    int c = 0;
    {
        const unsigned* sec4 = (const unsigned*)(sec + r0);
        for (int t = lane; t < R / 4; t += 32)
            c += __popc(__vcmpeq4(sec4[t], pat) & 0x01010101u);
        c = __reduce_add_sync(0xffffffffu, c);
    }
    if (lane == 0) wcnt[wid] = c;
    __syncthreads();
    if (wid == 0) {
        int v = wcnt[lane];
        int orig = v;
        #pragma unroll
        for (int o = 1; o < 32; o <<= 1) {
            int u = __shfl_up_sync(0xffffffffu, v, o);
            if (lane >= o) v += u;
        }
        woff[lane] = v - orig;
        if (lane == 31) g_cnt[b][s] = v;
    }
    __syncthreads();
    // STABLE scatter: i = r0 + t*32 + lane  (lanes ascending == indices ascending)
    int pos = woff[wid];
    float4* __restrict__ comp = g_comp[bs];
    for (int t = 0; t < R / 32; t++) {
        int i = r0 + t * 32 + lane;
        bool f = (sec[i] == (unsigned char)s);
        unsigned m = __ballot_sync(0xffffffffu, f);
        if (f) {
            float4 q;
            q.x = pts[3 * i];
            q.y = pts[3 * i + 1];
            q.z = pts[3 * i + 2];
            q.w = __int_as_float(i);
            comp[pos + __popc(m & ((1u << lane) - 1u))] = q;
        }
        pos += __popc(m);
    }
}

// budget for (b, s): nk, off (prefix of earlier sectors' nk), st (sum of all nk)
__device__ __forceinline__ void budget(int b, int s, int& nk, int& off, int& st) {
    int cs[7];
    #pragma unroll
    for (int t = 0; t < 7; t++) cs[t] = g_cnt[b][t];
    int total = cs[0] + cs[1] + cs[2] + cs[3] + cs[4] + cs[5] + cs[6];
    if (total < 1) total = 1;
    off = 0; nk = 0; st = 0;
    #pragma unroll
    for (int t = 0; t < NS; t++) {
        float q = __fdiv_rn(__fmul_rn((float)cs[t], 2048.0f), (float)total);
        int n = (int)ceilf(q);
        if (n > cs[t]) n = cs[t];
        if (t < s) off += n;
        if (t == s) nk = n;
        st += n;
    }
}

// ---- FPS v9: value-only loop, per-warp index pre-resolve, ONE barrier/iter ----
template<int P>
__device__ __forceinline__ void fps_loop(
    int off, int st, int nEff, int cnt,
    const float4* __restrict__ sP,
    float (*sVal)[NW], int (*sId)[NW], float* __restrict__ out)
{
    int tid = threadIdx.x, lane = tid & 31, wid = tid >> 5;
    u64 pxp[P], pyp[P], pzp[P];
    float dm[2 * P];
    #pragma unroll
    for (int p = 0; p < P; p++) {
        int i0 = (2 * p) * FT + tid, i1 = (2 * p + 1) * FT + tid;
        float x0 = 0, y0 = 0, z0 = 0, x1 = 0, y1 = 0, z1 = 0;
        if (i0 < cnt) { float4 q = sP[i0]; x0 = q.x; y0 = q.y; z0 = q.z;
                        dm[2 * p] = CUDART_INF_F; }
        else dm[2 * p] = -CUDART_INF_F;
        if (i1 < cnt) { float4 q = sP[i1]; x1 = q.x; y1 = q.y; z1 = q.z;
                        dm[2 * p + 1] = CUDART_INF_F; }
        else dm[2 * p + 1] = -CUDART_INF_F;
        pxp[p] = f2pack(x0, x1); pyp[p] = f2pack(y0, y1); pzp[p] = f2pack(z0, z1);
    }
    float4 pv0 = sP[0];
    float lx = pv0.x, ly = pv0.y, lz = pv0.z;
    if (tid == 0) {                                  // pick 0 output (+cyclic repeats)
        int q = off;
        do { float* o3 = out + (size_t)q * 3;
             o3[0] = pv0.x; o3[1] = pv0.y; o3[2] = pv0.z; q += st; } while (q < KK);
    }

    for (int j = 1; j < nEff; j++) {
        int par = j & 1;
        u64 nlx = f2pack(-lx, -lx), nly = f2pack(-ly, -ly), nlz = f2pack(-lz, -lz);
        float vmax = -CUDART_INF_F;
        #pragma unroll
        for (int p = 0; p < P; p++) {
            u64 ax = add2(pxp[p], nlx);
            u64 ay = add2(pyp[p], nly);
            u64 az = add2(pzp[p], nlz);
            u64 d2p = add2(add2(mul2(ax, ax), mul2(ay, ay)), mul2(az, az));
            float d2a, d2b; f2unpack(d2p, d2a, d2b);
            float a = fminf(dm[2 * p], d2a);          // -inf slots stay -inf
            float c = fminf(dm[2 * p + 1], d2b);
            dm[2 * p] = a; dm[2 * p + 1] = c;
            vmax = fmaxf(vmax, fmaxf(a, c));
        }
        // per-warp: max value + lowest global slot achieving it (pre-barrier)
        unsigned vb = (vmax < 0.0f) ? 0u : __float_as_uint(vmax);
        unsigned wm = __reduce_max_sync(0xffffffffu, vb);    // bits order-iso for >= 0
        int cand = 0x7fffffff;
        if (vb == wm && vmax >= 0.0f) {              // ~1 lane/warp (dead lanes excluded)
            #pragma unroll
            for (int k = 2 * P - 1; k >= 0; k--)     // ends at lowest matching slot
                if (dm[k] == vmax) cand = k * FT + tid;
        }
        cand = (int)__reduce_min_sync(0xffffffffu, (unsigned)cand);
        if (lane == 0) { sVal[par][wid] = __uint_as_float(wm); sId[par][wid] = cand; }
        __syncthreads();                             // the ONLY barrier per pick
        // every thread: value tree + index select (no atomics, no 2nd barrier)
        float4 v0 = *(const float4*)&sVal[par][0];
        float4 v1 = *(const float4*)&sVal[par][4];
        float bm = fmaxf(fmaxf(fmaxf(v0.x, v0.y), fmaxf(v0.z, v0.w)),
                         fmaxf(fmaxf(v1.x, v1.y), fmaxf(v1.z, v1.w)));
        int4 j0 = *(const int4*)&sId[par][0];
        int4 j1 = *(const int4*)&sId[par][4];
        int w0 = (v0.x == bm) ? j0.x : 0x7fffffff;
        int w1 = (v0.y == bm) ? j0.y : 0x7fffffff;
        int w2 = (v0.z == bm) ? j0.z : 0x7fffffff;
        int w3 = (v0.w == bm) ? j0.w : 0x7fffffff;
        int w4 = (v1.x == bm) ? j1.x : 0x7fffffff;
        int w5 = (v1.y == bm) ? j1.y : 0x7fffffff;
        int w6 = (v1.z == bm) ? j1.z : 0x7fffffff;
        int w7 = (v1.w == bm) ? j1.w : 0x7fffffff;
        int widx = min(min(min(w0, w1), min(w2, w3)), min(min(w4, w5), min(w6, w7)));
        float4 pw = sP[widx];                        // single LDS.128 broadcast
        lx = pw.x; ly = pw.y; lz = pw.z;
        if (tid == 0) {
            int q = off + j;
            do { float* o3 = out + (size_t)q * 3;
                 o3[0] = pw.x; o3[1] = pw.y; o3[2] = pw.z; q += st; } while (q < KK);
        }
    }
}

__global__ void __launch_bounds__(FT) k_fps(const float* __restrict__ points,
                                            float* __restrict__ outAll) {
    extern __shared__ float4 sP[];                   // [CAP]
    __shared__ __align__(16) float sVal[2][NW];
    __shared__ __align__(16) int   sId[2][NW];
    __shared__ unsigned fV[2][NW], fI[2][NW];        // fallback reduction scratch

    int bs = blockIdx.x;
    int b = bs / NS, s = bs - b * NS;
    int cnt = g_cnt[b][s];
    int nk, off, st;
    budget(b, s, nk, off, st);
    float* __restrict__ out = outAll + (size_t)b * KK * 3;

    int tid = threadIdx.x, lane = tid & 31, wid = tid >> 5;

    if (st < 1) {                                    // no picks anywhere in batch b
        if (s == 0) {                                // reference: zero buf -> points[b][0]
            const float* p0 = points + (size_t)b * NP * 3;
            float x = p0[0], y = p0[1], z = p0[2];
            for (int i = tid; i < KK; i += FT) {
                out[3 * i] = x; out[3 * i + 1] = y; out[3 * i + 2] = z;
            }
        }
        return;
    }
    if (nk <= 0 || off >= KK) return;
    int nEff = nk;
    if (off + nEff > KK) nEff = KK - off;

    const float4* __restrict__ comp = g_comp[bs];

    if (cnt <= CAP) {
        for (int i = tid; i < cnt; i += FT) sP[i] = comp[i];
        __syncthreads();
        int pairs = (cnt + 2 * FT - 1) / (2 * FT);
        switch (pairs) {
            case 1:  fps_loop<1>(off, st, nEff, cnt, sP, sVal, sId, out); break;
            case 2:  fps_loop<2>(off, st, nEff, cnt, sP, sVal, sId, out); break;
            case 3:  fps_loop<3>(off, st, nEff, cnt, sP, sVal, sId, out); break;
            case 4:  fps_loop<4>(off, st, nEff, cnt, sP, sVal, sId, out); break;
            case 5:  fps_loop<5>(off, st, nEff, cnt, sP, sVal, sId, out); break;
            case 6:  fps_loop<6>(off, st, nEff, cnt, sP, sVal, sId, out); break;
            case 7:  fps_loop<7>(off, st, nEff, cnt, sP, sVal, sId, out); break;
            case 8:  fps_loop<8>(off, st, nEff, cnt, sP, sVal, sId, out); break;
            case 9:  fps_loop<9>(off, st, nEff, cnt, sP, sVal, sId, out); break;
            case 10: fps_loop<10>(off, st, nEff, cnt, sP, sVal, sId, out); break;
            case 11: fps_loop<11>(off, st, nEff, cnt, sP, sVal, sId, out); break;
            default: fps_loop<12>(off, st, nEff, cnt, sP, sVal, sId, out); break;
        }
    } else {
        // ---- gmem fallback (rare; correctness net) — proven 2-barrier scheme ----
        float* __restrict__ D = g_dmin[bs];
        float4 p0 = comp[0];
        float lx = p0.x, ly = p0.y, lz = p0.z;
        if (tid == 0) {
            int q = off;
            do { float* o3 = out + (size_t)q * 3;
                 o3[0] = p0.x; o3[1] = p0.y; o3[2] = p0.z; q += st; } while (q < KK);
        }
        for (int j = 1; j < nEff; j++) {
            float vmax = -CUDART_INF_F;
            unsigned vidx = 0x7fffffffu;
            for (int i = tid; i < cnt; i += FT) {
                float4 p = comp[i];
                float ax = __fsub_rn(p.x, lx), ay = __fsub_rn(p.y, ly), az = __fsub_rn(p.z, lz);
                float d2 = __fadd_rn(__fadd_rn(__fmul_rn(ax, ax), __fmul_rn(ay, ay)),
                                     __fmul_rn(az, az));
                float dmn = (j == 1) ? d2 : fminf(D[i], d2);
                D[i] = dmn;
                if (dmn > vmax) { vmax = dmn; vidx = (unsigned)i; }
            }
            unsigned vb = (vmax < 0.0f) ? 0u : __float_as_uint(vmax);
            unsigned wm = __reduce_max_sync(0xffffffffu, vb);
            unsigned ci = (vb == wm) ? vidx : 0xffffffffu;
            unsigned wi = __reduce_min_sync(0xffffffffu, ci);
            int par = j & 1;
            if (lane == 0) { fV[par][wid] = wm; fI[par][wid] = wi; }
            __syncthreads();
            unsigned bv = fV[par][0], bp = fI[par][0];
            #pragma unroll
            for (int w2 = 1; w2 < NW; w2++) {
                unsigned v = fV[par][w2], i2 = fI[par][w2];
                if (v > bv || (v == bv && i2 < bp)) { bv = v; bp = i2; }
            }
            float4 pw = comp[bp];
            lx = pw.x; ly = pw.y; lz = pw.z;
            if (tid == 0) {
                int q = off + j;
                do { float* o3 = out + (size_t)q * 3;
                     o3[0] = pw.x; o3[1] = pw.y; o3[2] = pw.z; q += st; } while (q < KK);
            }
        }
    }
}

extern "C" void kernel_launch(void* const* d_in, const int* in_sizes, int n_in,
                              void* d_out, int out_size) {
    const float* points = (const float*)d_in[0];  // [2,65536,3] f32
    const float* rois   = (const float*)d_in[1];  // [2,128,7]  f32
    float* out = (float*)d_out;                   // [2,2048,3] f32

    cudaFuncSetAttribute(k_fps, cudaFuncAttributeMaxDynamicSharedMemorySize, SMEM_FPS);

    dim3 gc(NP / 512, BN);
    k_classify<<<gc, 256>>>(points, rois);
    k_compact<<<NBS + BN, 1024>>>(points);
    k_fps<<<NBS, FT, SMEM_FPS>>>(points, out);
}

// round 13
// speedup vs baseline: 1.1323x; 1.1323x over previous
#include <cuda_runtime.h>
#include <math_constants.h>

#define BN 2
#define NP 65536
#define MR 128
#define NS 6
#define KK 2048
#define NBS (BN*NS)

#define FT 256          // FPS threads (8 warps -> 2 per SMSP)
#define NW (FT/32)      // 8 warps
#define MAXP 12         // max candidate pairs per thread
#define CAP (FT*2*MAXP) // 6144 candidates
#define SMEM_FPS (CAP*16)    // float4 sP[CAP]

typedef unsigned long long u64;
__device__ __forceinline__ u64 f2pack(float lo, float hi) {
    u64 r; asm("mov.b64 %0,{%1,%2};" : "=l"(r) : "f"(lo), "f"(hi)); return r;
}
__device__ __forceinline__ void f2unpack(u64 v, float& lo, float& hi) {
    asm("mov.b64 {%0,%1},%2;" : "=f"(lo), "=f"(hi) : "l"(v));
}
__device__ __forceinline__ u64 add2(u64 a, u64 b) {
    u64 r; asm("add.rn.f32x2 %0,%1,%2;" : "=l"(r) : "l"(a), "l"(b)); return r;
}
__device__ __forceinline__ u64 mul2(u64 a, u64 b) {
    u64 r; asm("mul.rn.f32x2 %0,%1,%2;" : "=l"(r) : "l"(a), "l"(b)); return r;
}

// ---- scratch (__device__ globals: allocation-free) ----
__device__ float4        g_comp[NBS][NP];   // compacted candidates (x,y,z, orig idx bits)
__device__ float         g_dmin[NBS][NP];   // FPS fallback dmin (cnt > CAP only)
__device__ unsigned char g_sec [BN][NP];    // sector code 0..6, 255 = invalid
__device__ int g_cnt[BN][7];                // per-sector counts; [6] = valid-but-sector-6

// ---- classify: 2 points/thread, packed-f32x2 distances (exact), deferred sqrt cleanup ----
__global__ void __launch_bounds__(256) k_classify(const float* __restrict__ points,
                                                  const float* __restrict__ rois) {
    __shared__ __align__(8) float sncx[MR], sncy[MR], sncz[MR];  // NEGATED centers
    __shared__ float sthr[MR];                                   // maxdim + 1.6
    int b = blockIdx.y;
    int tid = threadIdx.x;
    if (tid < MR) {
        const float* r = rois + (b * MR + tid) * 7;
        float cx = r[0], cy = r[1], cz = r[2];
        float dx = r[3], dy = r[4], dz = r[5];
        cz = __fadd_rn(cz, __fmul_rn(dz, 0.5f));
        float hx = __fmul_rn(dx, 0.5f), hy = __fmul_rn(dy, 0.5f), hz = __fmul_rn(dz, 0.5f);
        float md = __fsqrt_rn(__fadd_rn(__fadd_rn(__fmul_rn(hx, hx), __fmul_rn(hy, hy)),
                                        __fmul_rn(hz, hz)));
        sncx[tid] = -cx; sncy[tid] = -cy; sncz[tid] = -cz;
        sthr[tid] = __fadd_rn(md, 1.6f);
    }
    __syncthreads();

    int i0 = blockIdx.x * 512 + tid;
    int i1 = i0 + 256;
    const float* pA = points + ((size_t)b * NP + i0) * 3;
    const float* pB = points + ((size_t)b * NP + i1) * 3;
    float pxA = pA[0], pyA = pA[1], pzA = pA[2];
    float pxB = pB[0], pyB = pB[1], pzB = pB[2];
    u64 pxa = f2pack(pxA, pxA), pya = f2pack(pyA, pyA), pza = f2pack(pzA, pzA);
    u64 pxb = f2pack(pxB, pxB), pyb = f2pack(pyB, pyB), pzb = f2pack(pzB, pzB);

    // p - c == p + (-c) exactly (IEEE). Packed halves round identically to scalar rn.
    float m1A = CUDART_INF_F, m2A = CUDART_INF_F; int biA = 0;
    float m1B = CUDART_INF_F, m2B = CUDART_INF_F; int biB = 0;
    #pragma unroll 4
    for (int m = 0; m < MR / 2; m++) {
        u64 ncx = *(const u64*)&sncx[2 * m];
        u64 ncy = *(const u64*)&sncy[2 * m];
        u64 ncz = *(const u64*)&sncz[2 * m];
        u64 axA = add2(pxa, ncx), ayA = add2(pya, ncy), azA = add2(pza, ncz);
        u64 d2A = add2(add2(mul2(axA, axA), mul2(ayA, ayA)), mul2(azA, azA));
        u64 axB = add2(pxb, ncx), ayB = add2(pyb, ncy), azB = add2(pzb, ncz);
        u64 d2B = add2(add2(mul2(axB, axB), mul2(ayB, ayB)), mul2(azB, azB));
        float a0, a1, b0, b1;
        f2unpack(d2A, a0, a1);
        f2unpack(d2B, b0, b1);
        float mx = fmaxf(a0, m1A); m2A = fminf(m2A, mx);
        if (a0 < m1A) { m1A = a0; biA = 2 * m; }
        mx = fmaxf(a1, m1A); m2A = fminf(m2A, mx);
        if (a1 < m1A) { m1A = a1; biA = 2 * m + 1; }
        mx = fmaxf(b0, m1B); m2B = fminf(m2B, mx);
        if (b0 < m1B) { m1B = b0; biB = 2 * m; }
        mx = fmaxf(b1, m1B); m2B = fminf(m2B, mx);
        if (b1 < m1B) { m1B = b1; biB = 2 * m + 1; }
    }

    #pragma unroll
    for (int pt = 0; pt < 2; pt++) {
        float px = pt ? pxB : pxA, py = pt ? pyB : pyA, pz = pt ? pzB : pzA;
        float m1 = pt ? m1B : m1A, m2 = pt ? m2B : m2A;
        int bi = pt ? biB : biA;
        float s1 = __fsqrt_rn(m1);
        // d2-argmin == sqrt-argmin unless two d2 round to the same sqrt; redo exactly.
        if (__fsqrt_rn(m2) == s1) {
            float bsv = CUDART_INF_F; int bi2 = 0;
            for (int m = 0; m < MR; m++) {
                float ax = __fadd_rn(px, sncx[m]);
                float ay = __fadd_rn(py, sncy[m]);
                float az = __fadd_rn(pz, sncz[m]);
                float d2 = __fadd_rn(__fadd_rn(__fmul_rn(ax, ax), __fmul_rn(ay, ay)),
                                     __fmul_rn(az, az));
                float sd = __fsqrt_rn(d2);
                if (sd < bsv) { bsv = sd; bi2 = m; }
            }
            s1 = bsv; bi = bi2;
        }
        bool valid = s1 < sthr[bi];
        float ang = __fadd_rn(atan2f(py, px), 3.14159265358979323846f);
        float fs  = floorf(__fdiv_rn(ang, 1.04719755119659774615f));
        fs = fminf(fmaxf(fs, 0.0f), 6.0f);
        int s = (int)fs;
        g_sec[b][pt ? i1 : i0] = valid ? (unsigned char)s : (unsigned char)255;
    }
}

// ---- compact: vcmpeq4 counting + per-lane-4 STABLE vectorized scatter ----
// Stability proof: lane L owns 4 CONSECUTIVE indices [i0, i0+4); exclusive prefix of
// per-lane counts gives ascending bases for ascending lanes; within a lane, bytes are
// written in ascending index order. Warps own disjoint ascending ranges (r0 = wid*R).
__global__ void __launch_bounds__(1024) k_compact(const float* __restrict__ points) {
    int bs = blockIdx.x;
    int tid = threadIdx.x, lane = tid & 31, wid = tid >> 5;
    __shared__ int wcnt[32];
    __shared__ int woff[32];

    if (bs >= NBS) {  // count-only: sector 6 of batch b
        int b = bs - NBS;
        const unsigned* sec4 = (const unsigned*)g_sec[b];
        int c = 0;
        for (int i = tid; i < NP / 4; i += 1024)
            c += __popc(__vcmpeq4(sec4[i], 0x06060606u) & 0x01010101u);
        c = __reduce_add_sync(0xffffffffu, c);
        if (lane == 0) wcnt[wid] = c;
        __syncthreads();
        if (tid == 0) {
            int t = 0;
            for (int w = 0; w < 32; w++) t += wcnt[w];
            g_cnt[b][6] = t;
        }
        return;
    }

    int b = bs / NS, s = bs - b * NS;
    const unsigned char* sec = g_sec[b];
    const float* pts = points + (size_t)b * NP * 3;
    const int R = NP / 32;           // 2048 points per warp, contiguous (stable order)
    int r0 = wid * R;
    unsigned pat = 0x01010101u * (unsigned)s;

    int c = 0;
    {
        const unsigned* sec4 = (const unsigned*)(sec + r0);
        for (int t = lane; t < R / 4; t += 32)
            c += __popc(__vcmpeq4(sec4[t], pat) & 0x01010101u);
        c = __reduce_add_sync(0xffffffffu, c);
    }
    if (lane == 0) wcnt[wid] = c;
    __syncthreads();
    if (wid == 0) {
        int v = wcnt[lane];
        int orig = v;
        #pragma unroll
        for (int o = 1; o < 32; o <<= 1) {
            int u = __shfl_up_sync(0xffffffffu, v, o);
            if (lane >= o) v += u;
        }
        woff[lane] = v - orig;
        if (lane == 31) g_cnt[b][s] = v;
    }
    __syncthreads();
    int pos = woff[wid];
    float4* __restrict__ comp = g_comp[bs];
    for (int t = 0; t < R / 128; t++) {
        int i0 = r0 + t * 128 + lane * 4;
        unsigned w4 = *(const unsigned*)(sec + i0);
        unsigned eq = __vcmpeq4(w4, pat) & 0x01010101u;
        int cc = __popc(eq);
        int ex = cc;
        #pragma unroll
        for (int o = 1; o < 32; o <<= 1) {
            int u = __shfl_up_sync(0xffffffffu, ex, o);
            if (lane >= o) ex += u;
        }
        int wsum = __shfl_sync(0xffffffffu, ex, 31);
        ex -= cc;
        int base = pos + ex;
        int o2 = 0;
        if (eq & 0x1u) {
            comp[base + o2] = make_float4(pts[3*i0], pts[3*i0+1], pts[3*i0+2],
                                          __int_as_float(i0)); o2++;
        }
        if (eq & 0x100u) {
            int i = i0 + 1;
            comp[base + o2] = make_float4(pts[3*i], pts[3*i+1], pts[3*i+2],
                                          __int_as_float(i)); o2++;
        }
        if (eq & 0x10000u) {
            int i = i0 + 2;
            comp[base + o2] = make_float4(pts[3*i], pts[3*i+1], pts[3*i+2],
                                          __int_as_float(i)); o2++;
        }
        if (eq & 0x1000000u) {
            int i = i0 + 3;
            comp[base + o2] = make_float4(pts[3*i], pts[3*i+1], pts[3*i+2],
                                          __int_as_float(i));
        }
        pos += wsum;
    }
}

// budget for (b, s): nk, off (prefix of earlier sectors' nk), st (sum of all nk)
__device__ __forceinline__ void budget(int b, int s, int& nk, int& off, int& st) {
    int cs[7];
    #pragma unroll
    for (int t = 0; t < 7; t++) cs[t] = g_cnt[b][t];
    int total = cs[0] + cs[1] + cs[2] + cs[3] + cs[4] + cs[5] + cs[6];
    if (total < 1) total = 1;
    off = 0; nk = 0; st = 0;
    #pragma unroll
    for (int t = 0; t < NS; t++) {
        float q = __fdiv_rn(__fmul_rn((float)cs[t], 2048.0f), (float)total);
        int n = (int)ceilf(q);
        if (n > cs[t]) n = cs[t];
        if (t < s) off += n;
        if (t == s) nk = n;
        st += n;
    }
}

// ---- FPS (R10-proven, 163.8us): value-only loop, lazy index post-barrier, 2 bars ----
template<int P>
__device__ __forceinline__ void fps_loop(
    int off, int st, int nEff, int cnt,
    const float4* __restrict__ sP,
    float (*sV)[NW], int* sIdx, float* __restrict__ out)
{
    int tid = threadIdx.x, lane = tid & 31, wid = tid >> 5;
    u64 pxp[P], pyp[P], pzp[P];
    float dm[2 * P];
    #pragma unroll
    for (int p = 0; p < P; p++) {
        int i0 = (2 * p) * FT + tid, i1 = (2 * p + 1) * FT + tid;
        float x0 = 0, y0 = 0, z0 = 0, x1 = 0, y1 = 0, z1 = 0;
        if (i0 < cnt) { float4 q = sP[i0]; x0 = q.x; y0 = q.y; z0 = q.z;
                        dm[2 * p] = CUDART_INF_F; }
        else dm[2 * p] = -CUDART_INF_F;
        if (i1 < cnt) { float4 q = sP[i1]; x1 = q.x; y1 = q.y; z1 = q.z;
                        dm[2 * p + 1] = CUDART_INF_F; }
        else dm[2 * p + 1] = -CUDART_INF_F;
        pxp[p] = f2pack(x0, x1); pyp[p] = f2pack(y0, y1); pzp[p] = f2pack(z0, z1);
    }
    float4 pv0 = sP[0];
    float lx = pv0.x, ly = pv0.y, lz = pv0.z;
    if (tid == 0) {                                  // pick 0 output (+cyclic repeats)
        int q = off;
        do { float* o3 = out + (size_t)q * 3;
             o3[0] = pv0.x; o3[1] = pv0.y; o3[2] = pv0.z; q += st; } while (q < KK);
    }

    for (int j = 1; j < nEff; j++) {
        int par = j & 1;
        u64 nlx = f2pack(-lx, -lx), nly = f2pack(-ly, -ly), nlz = f2pack(-lz, -lz);
        float vmax = -CUDART_INF_F;
        #pragma unroll
        for (int p = 0; p < P; p++) {
            u64 ax = add2(pxp[p], nlx);
            u64 ay = add2(pyp[p], nly);
            u64 az = add2(pzp[p], nlz);
            u64 d2p = add2(add2(mul2(ax, ax), mul2(ay, ay)), mul2(az, az));
            float d2a, d2b; f2unpack(d2p, d2a, d2b);
            float a = fminf(dm[2 * p], d2a);          // -inf slots stay -inf
            float c = fminf(dm[2 * p + 1], d2b);
            dm[2 * p] = a; dm[2 * p + 1] = c;
            vmax = fmaxf(vmax, fmaxf(a, c));
        }
        unsigned vb = (vmax < 0.0f) ? 0u : __float_as_uint(vmax);
        unsigned wm = __reduce_max_sync(0xffffffffu, vb);    // bits order-iso for >= 0
        if (lane == 0) sV[par][wid] = __uint_as_float(wm);
        __syncthreads();
        if (tid == 0) sIdx[par ^ 1] = 0x7fffffff;   // reset other parity (safe window)
        // blockmax: 2 vector LDS + 7 FMNMX, value only
        float4 v0 = *(const float4*)&sV[par][0];
        float4 v1 = *(const float4*)&sV[par][4];
        float bm = fmaxf(fmaxf(fmaxf(v0.x, v0.y), fmaxf(v0.z, v0.w)),
                         fmaxf(fmaxf(v1.x, v1.y), fmaxf(v1.z, v1.w)));
        if (vmax == bm) {                            // ~1 warp; dead threads (-inf) never
            int cand = 0x7fffffff;
            #pragma unroll
            for (int k = 2 * P - 1; k >= 0; k--)     // ends at lowest matching slot
                if (dm[k] == bm) cand = k * FT + tid;
            atomicMin(&sIdx[par], cand);             // lowest compacted idx = exact tie-break
        }
        __syncthreads();
        int widx = sIdx[par];
        float4 pw = sP[widx];                        // single LDS.128 broadcast
        lx = pw.x; ly = pw.y; lz = pw.z;
        if (tid == 0) {
            int q = off + j;
            do { float* o3 = out + (size_t)q * 3;
                 o3[0] = pw.x; o3[1] = pw.y; o3[2] = pw.z; q += st; } while (q < KK);
        }
    }
}

__global__ void __launch_bounds__(FT) k_fps(const float* __restrict__ points,
                                            float* __restrict__ outAll) {
    extern __shared__ float4 sP[];                   // [CAP]
    __shared__ __align__(16) float sV[2][NW];
    __shared__ int sIdx[2];
    __shared__ unsigned fV[2][NW], fI[2][NW];        // fallback reduction scratch

    int bs = blockIdx.x;
    int b = bs / NS, s = bs - b * NS;
    int cnt = g_cnt[b][s];
    int nk, off, st;
    budget(b, s, nk, off, st);
    float* __restrict__ out = outAll + (size_t)b * KK * 3;

    int tid = threadIdx.x, lane = tid & 31, wid = tid >> 5;

    if (st < 1) {                                    // no picks anywhere in batch b
        if (s == 0) {                                // reference: zero buf -> points[b][0]
            const float* p0 = points + (size_t)b * NP * 3;
            float x = p0[0], y = p0[1], z = p0[2];
            for (int i = tid; i < KK; i += FT) {
                out[3 * i] = x; out[3 * i + 1] = y; out[3 * i + 2] = z;
            }
        }
        return;
    }
    if (nk <= 0 || off >= KK) return;
    int nEff = nk;
    if (off + nEff > KK) nEff = KK - off;

    const float4* __restrict__ comp = g_comp[bs];

    if (cnt <= CAP) {
        for (int i = tid; i < cnt; i += FT) sP[i] = comp[i];
        if (tid == 0) { sIdx[0] = 0x7fffffff; sIdx[1] = 0x7fffffff; }
        __syncthreads();
        int pairs = (cnt + 2 * FT - 1) / (2 * FT);
        switch (pairs) {
            case 1:  fps_loop<1>(off, st, nEff, cnt, sP, sV, sIdx, out); break;
            case 2:  fps_loop<2>(off, st, nEff, cnt, sP, sV, sIdx, out); break;
            case 3:  fps_loop<3>(off, st, nEff, cnt, sP, sV, sIdx, out); break;
            case 4:  fps_loop<4>(off, st, nEff, cnt, sP, sV, sIdx, out); break;
            case 5:  fps_loop<5>(off, st, nEff, cnt, sP, sV, sIdx, out); break;
            case 6:  fps_loop<6>(off, st, nEff, cnt, sP, sV, sIdx, out); break;
            case 7:  fps_loop<7>(off, st, nEff, cnt, sP, sV, sIdx, out); break;
            case 8:  fps_loop<8>(off, st, nEff, cnt, sP, sV, sIdx, out); break;
            case 9:  fps_loop<9>(off, st, nEff, cnt, sP, sV, sIdx, out); break;
            case 10: fps_loop<10>(off, st, nEff, cnt, sP, sV, sIdx, out); break;
            case 11: fps_loop<11>(off, st, nEff, cnt, sP, sV, sIdx, out); break;
            default: fps_loop<12>(off, st, nEff, cnt, sP, sV, sIdx, out); break;
        }
    } else {
        // ---- gmem fallback (rare; correctness net) — proven 2-barrier scheme ----
        float* __restrict__ D = g_dmin[bs];
        float4 p0 = comp[0];
        float lx = p0.x, ly = p0.y, lz = p0.z;
        if (tid == 0) {
            int q = off;
            do { float* o3 = out + (size_t)q * 3;
                 o3[0] = p0.x; o3[1] = p0.y; o3[2] = p0.z; q += st; } while (q < KK);
        }
        for (int j = 1; j < nEff; j++) {
            float vmax = -CUDART_INF_F;
            unsigned vidx = 0x7fffffffu;
            for (int i = tid; i < cnt; i += FT) {
                float4 p = comp[i];
                float ax = __fsub_rn(p.x, lx), ay = __fsub_rn(p.y, ly), az = __fsub_rn(p.z, lz);
                float d2 = __fadd_rn(__fadd_rn(__fmul_rn(ax, ax), __fmul_rn(ay, ay)),
                                     __fmul_rn(az, az));
                float dmn = (j == 1) ? d2 : fminf(D[i], d2);
                D[i] = dmn;
                if (dmn > vmax) { vmax = dmn; vidx = (unsigned)i; }
            }
            unsigned vb = (vmax < 0.0f) ? 0u : __float_as_uint(vmax);
            unsigned wm = __reduce_max_sync(0xffffffffu, vb);
            unsigned ci = (vb == wm) ? vidx : 0xffffffffu;
            unsigned wi = __reduce_min_sync(0xffffffffu, ci);
            int par = j & 1;
            if (lane == 0) { fV[par][wid] = wm; fI[par][wid] = wi; }
            __syncthreads();
            unsigned bv = fV[par][0], bp = fI[par][0];
            #pragma unroll
            for (int w2 = 1; w2 < NW; w2++) {
                unsigned v = fV[par][w2], i2 = fI[par][w2];
                if (v > bv || (v == bv && i2 < bp)) { bv = v; bp = i2; }
            }
            float4 pw = comp[bp];
            lx = pw.x; ly = pw.y; lz = pw.z;
            if (tid == 0) {
                int q = off + j;
                do { float* o3 = out + (size_t)q * 3;
                     o3[0] = pw.x; o3[1] = pw.y; o3[2] = pw.z; q += st; } while (q < KK);
            }
        }
    }
}

extern "C" void kernel_launch(void* const* d_in, const int* in_sizes, int n_in,
                              void* d_out, int out_size) {
    const float* points = (const float*)d_in[0];  // [2,65536,3] f32
    const float* rois   = (const float*)d_in[1];  // [2,128,7]  f32
    float* out = (float*)d_out;                   // [2,2048,3] f32

    cudaFuncSetAttribute(k_fps, cudaFuncAttributeMaxDynamicSharedMemorySize, SMEM_FPS);

    dim3 gc(NP / 512, BN);
    k_classify<<<gc, 256>>>(points, rois);
    k_compact<<<NBS + BN, 1024>>>(points);
    k_fps<<<NBS, FT, SMEM_FPS>>>(points, out);
}